// round 3
// baseline (speedup 1.0000x reference)
#include <cuda_runtime.h>

#define N_NODES 100000
#define N_EDGES 1600000
#define NHEAD 4
#define HIDD 64
#define CDIM 256   // H*HID = IN_DIM = OUT_DIM
#define NEG_SLOPE 0.2f

// ---------------- scratch (static device globals; no runtime allocation) ----
__device__ float    g_xw [ (size_t)N_NODES * CDIM ];   // x @ W  (node features per head)
__device__ float    g_acc[ (size_t)N_NODES * CDIM ];   // unnormalized aggregated messages
__device__ float    g_e  [ (size_t)N_EDGES * NHEAD ];  // per-edge logits (post leaky-relu)
__device__ float    g_s1 [ (size_t)N_NODES * NHEAD ];  // xw . a1
__device__ float    g_s2 [ (size_t)N_NODES * NHEAD ];  // xw . a2
__device__ unsigned g_umax[(size_t)N_NODES * NHEAD ];  // encoded segment max
__device__ float    g_ssum[(size_t)N_NODES * NHEAD ];  // segment sum of exp
__device__ float    g_w3 [ NHEAD * 16 ];               // W_edge @ a3

// order-preserving float<->uint encode for atomicMax on floats
__device__ __forceinline__ unsigned fenc(float f) {
    unsigned u = __float_as_uint(f);
    return (u & 0x80000000u) ? ~u : (u | 0x80000000u);
}
__device__ __forceinline__ float fdec(unsigned e) {
    return __uint_as_float((e & 0x80000000u) ? (e ^ 0x80000000u) : ~e);
}

// ---------------- zero init ------------------------------------------------
__global__ void k_zero() {
    long long i = (long long)blockIdx.x * blockDim.x + threadIdx.x;
    const long long nacc = (long long)N_NODES * CDIM;
    if (i < nacc) {
        g_acc[i] = 0.0f;
    } else {
        long long j = i - nacc;
        if (j < (long long)N_NODES * NHEAD) {
            g_ssum[j] = 0.0f;
            g_umax[j] = 0u;   // minimum in encoded order
        }
    }
}

// ---------------- w3[h][d] = sum_o W_edge[h][d][o] * a3[h][o] ---------------
__global__ void k_w3(const float* __restrict__ W_edge, const float* __restrict__ att) {
    int t = threadIdx.x;
    if (t >= NHEAD * 16) return;
    int h = t >> 4, d = t & 15;
    float s = 0.0f;
    #pragma unroll 8
    for (int o = 0; o < HIDD; ++o)
        s += W_edge[h * (16 * HIDD) + d * HIDD + o] * att[h * (3 * HIDD) + 2 * HIDD + o];
    g_w3[t] = s;
}

// ---------------- GEMM1: xw[n][h*64+o] = sum_i x[n][i] * W[h][i][o] ---------
__global__ __launch_bounds__(256) void k_gemm_xw(const float* __restrict__ X,
                                                 const float* __restrict__ W) {
    __shared__ float As[16][128];
    __shared__ float Bs[16][128];
    const int bm = blockIdx.x * 128;
    const int bn = blockIdx.y * 128;
    const int tid = threadIdx.x;
    const int tr = tid >> 4, tc = tid & 15;

    float acc[8][8];
    #pragma unroll
    for (int i = 0; i < 8; ++i)
        #pragma unroll
        for (int j = 0; j < 8; ++j) acc[i][j] = 0.0f;

    for (int k0 = 0; k0 < CDIM; k0 += 16) {
        #pragma unroll
        for (int it = 0; it < 2; ++it) {
            int f4  = tid + it * 256;       // 0..511
            int row = f4 >> 2;              // 0..127
            int col = (f4 & 3) << 2;        // 0,4,8,12
            int gr  = bm + row;
            float4 v = make_float4(0.f, 0.f, 0.f, 0.f);
            if (gr < N_NODES)
                v = *reinterpret_cast<const float4*>(X + (size_t)gr * CDIM + k0 + col);
            As[col + 0][row] = v.x; As[col + 1][row] = v.y;
            As[col + 2][row] = v.z; As[col + 3][row] = v.w;
        }
        #pragma unroll
        for (int it = 0; it < 2; ++it) {
            int f4   = tid + it * 256;      // 0..511
            int krow = f4 >> 5;             // 0..15
            int col  = (f4 & 31) << 2;      // 0..124
            int c    = bn + col;
            int k    = k0 + krow;
            // Wcat[k][c] = W[c>>6][k][c&63]
            float4 v = *reinterpret_cast<const float4*>(
                W + (size_t)(c >> 6) * (CDIM * HIDD) + (size_t)k * HIDD + (c & 63));
            *reinterpret_cast<float4*>(&Bs[krow][col]) = v;
        }
        __syncthreads();
        #pragma unroll
        for (int k = 0; k < 16; ++k) {
            float4 a0 = *reinterpret_cast<const float4*>(&As[k][tr * 8]);
            float4 a1 = *reinterpret_cast<const float4*>(&As[k][tr * 8 + 4]);
            float4 b0 = *reinterpret_cast<const float4*>(&Bs[k][tc * 8]);
            float4 b1 = *reinterpret_cast<const float4*>(&Bs[k][tc * 8 + 4]);
            float a[8] = {a0.x, a0.y, a0.z, a0.w, a1.x, a1.y, a1.z, a1.w};
            float b[8] = {b0.x, b0.y, b0.z, b0.w, b1.x, b1.y, b1.z, b1.w};
            #pragma unroll
            for (int i = 0; i < 8; ++i)
                #pragma unroll
                for (int j = 0; j < 8; ++j) acc[i][j] += a[i] * b[j];
        }
        __syncthreads();
    }
    #pragma unroll
    for (int i = 0; i < 8; ++i) {
        int gr = bm + tr * 8 + i;
        if (gr >= N_NODES) continue;
        float4 v0 = make_float4(acc[i][0], acc[i][1], acc[i][2], acc[i][3]);
        float4 v1 = make_float4(acc[i][4], acc[i][5], acc[i][6], acc[i][7]);
        *reinterpret_cast<float4*>(g_xw + (size_t)gr * CDIM + bn + tc * 8)     = v0;
        *reinterpret_cast<float4*>(g_xw + (size_t)gr * CDIM + bn + tc * 8 + 4) = v1;
    }
}

// ---------------- s1/s2: per-node dot of xw with a1/a2 (warp per node) -----
__global__ __launch_bounds__(256) void k_s12(const float* __restrict__ att) {
    __shared__ float a1s[CDIM];
    __shared__ float a2s[CDIM];
    int tid = threadIdx.x;
    {
        int h = tid >> 6, o = tid & 63;
        a1s[tid] = att[h * (3 * HIDD) + o];
        a2s[tid] = att[h * (3 * HIDD) + HIDD + o];
    }
    __syncthreads();
    int warp = tid >> 5, lane = tid & 31;
    long long n = (long long)blockIdx.x * 8 + warp;
    if (n >= N_NODES) return;
    const float4* xp = reinterpret_cast<const float4*>(g_xw + n * CDIM + lane * 8);
    float4 v0 = xp[0], v1 = xp[1];
    int base = lane * 8;
    float p1 = v0.x * a1s[base]     + v0.y * a1s[base + 1] + v0.z * a1s[base + 2] + v0.w * a1s[base + 3]
             + v1.x * a1s[base + 4] + v1.y * a1s[base + 5] + v1.z * a1s[base + 6] + v1.w * a1s[base + 7];
    float p2 = v0.x * a2s[base]     + v0.y * a2s[base + 1] + v0.z * a2s[base + 2] + v0.w * a2s[base + 3]
             + v1.x * a2s[base + 4] + v1.y * a2s[base + 5] + v1.z * a2s[base + 6] + v1.w * a2s[base + 7];
    #pragma unroll
    for (int off = 4; off; off >>= 1) {
        p1 += __shfl_down_sync(0xffffffffu, p1, off, 8);
        p2 += __shfl_down_sync(0xffffffffu, p2, off, 8);
    }
    if ((lane & 7) == 0) {
        int h = lane >> 3;
        g_s1[n * NHEAD + h] = p1;
        g_s2[n * NHEAD + h] = p2;
    }
}

// ---------------- edge pass A: logits + segment max -------------------------
__global__ __launch_bounds__(256) void k_edgeA(const int* __restrict__ ei,
                                               const float* __restrict__ eattr) {
    __shared__ float w3s[NHEAD * 16];
    if (threadIdx.x < NHEAD * 16) w3s[threadIdx.x] = g_w3[threadIdx.x];
    __syncthreads();
    long long id = (long long)blockIdx.x * 256 + threadIdx.x;
    if (id >= N_EDGES) return;
    int src = ei[id];
    int dst = ei[(long long)N_EDGES + id];
    if ((unsigned)src >= N_NODES || (unsigned)dst >= N_NODES) return;  // dtype canary
    const float4* ap = reinterpret_cast<const float4*>(eattr + id * 16);
    float4 e0 = ap[0], e1 = ap[1], e2 = ap[2], e3 = ap[3];
    float attr[16] = {e0.x, e0.y, e0.z, e0.w, e1.x, e1.y, e1.z, e1.w,
                      e2.x, e2.y, e2.z, e2.w, e3.x, e3.y, e3.z, e3.w};
    float4 s1v = *reinterpret_cast<const float4*>(g_s1 + (size_t)dst * NHEAD);
    float4 s2v = *reinterpret_cast<const float4*>(g_s2 + (size_t)src * NHEAD);
    float eh[NHEAD];
    #pragma unroll
    for (int h = 0; h < NHEAD; ++h) {
        float d = 0.0f;
        #pragma unroll
        for (int q = 0; q < 16; ++q) d += attr[q] * w3s[h * 16 + q];
        eh[h] = d;
    }
    eh[0] += s1v.x + s2v.x; eh[1] += s1v.y + s2v.y;
    eh[2] += s1v.z + s2v.z; eh[3] += s1v.w + s2v.w;
    #pragma unroll
    for (int h = 0; h < NHEAD; ++h) {
        eh[h] = (eh[h] >= 0.0f) ? eh[h] : NEG_SLOPE * eh[h];
        atomicMax(&g_umax[(size_t)dst * NHEAD + h], fenc(eh[h]));
    }
    *reinterpret_cast<float4*>(g_e + id * NHEAD) = make_float4(eh[0], eh[1], eh[2], eh[3]);
}

// ---------------- edge pass B: exp + segment sum + weighted scatter ---------
// one warp per edge; lane l handles feature cols [l*8, l*8+8)
__global__ __launch_bounds__(256) void k_edgeB(const int* __restrict__ ei) {
    long long id = ((long long)blockIdx.x * 256 + threadIdx.x) >> 5;
    int lane = threadIdx.x & 31;
    if (id >= N_EDGES) return;
    int src = ei[id];
    int dst = ei[(long long)N_EDGES + id];
    if ((unsigned)src >= N_NODES || (unsigned)dst >= N_NODES) return;  // dtype canary
    float4 ev = *reinterpret_cast<const float4*>(g_e + id * NHEAD);
    int h = lane >> 3;
    float eh = (h == 0) ? ev.x : (h == 1) ? ev.y : (h == 2) ? ev.z : ev.w;
    float m  = fdec(g_umax[(size_t)dst * NHEAD + h]);
    float ex = __expf(eh - m);
    if ((lane & 7) == 0) atomicAdd(&g_ssum[(size_t)dst * NHEAD + h], ex);
    const float4* xp = reinterpret_cast<const float4*>(g_xw + (size_t)src * CDIM + lane * 8);
    float4 v0 = xp[0], v1 = xp[1];
    float* dp = g_acc + (size_t)dst * CDIM + lane * 8;
    atomicAdd(dp + 0, v0.x * ex); atomicAdd(dp + 1, v0.y * ex);
    atomicAdd(dp + 2, v0.z * ex); atomicAdd(dp + 3, v0.w * ex);
    atomicAdd(dp + 4, v1.x * ex); atomicAdd(dp + 5, v1.y * ex);
    atomicAdd(dp + 6, v1.z * ex); atomicAdd(dp + 7, v1.w * ex);
}

// ---------------- normalize: acc /= (ssum + 1e-16) ---------------------------
__global__ void k_norm() {
    long long i = (long long)blockIdx.x * 256 + threadIdx.x;
    if (i >= (long long)N_NODES * CDIM) return;
    int c = (int)(i & (CDIM - 1));
    long long n = i >> 8;
    float s = g_ssum[n * NHEAD + (c >> 6)];
    g_acc[i] = g_acc[i] / (s + 1e-16f);
}

// ---------------- GEMM2: out = elu(accn @ proj_w + b) ------------------------
__global__ __launch_bounds__(256) void k_gemm_out(const float* __restrict__ PW,
                                                  const float* __restrict__ PB,
                                                  float* __restrict__ out) {
    __shared__ float As[16][128];
    __shared__ float Bs[16][128];
    const int bm = blockIdx.x * 128;
    const int bn = blockIdx.y * 128;
    const int tid = threadIdx.x;
    const int tr = tid >> 4, tc = tid & 15;

    float acc[8][8];
    #pragma unroll
    for (int i = 0; i < 8; ++i)
        #pragma unroll
        for (int j = 0; j < 8; ++j) acc[i][j] = 0.0f;

    for (int k0 = 0; k0 < CDIM; k0 += 16) {
        #pragma unroll
        for (int it = 0; it < 2; ++it) {
            int f4  = tid + it * 256;
            int row = f4 >> 2;
            int col = (f4 & 3) << 2;
            int gr  = bm + row;
            float4 v = make_float4(0.f, 0.f, 0.f, 0.f);
            if (gr < N_NODES)
                v = *reinterpret_cast<const float4*>(g_acc + (size_t)gr * CDIM + k0 + col);
            As[col + 0][row] = v.x; As[col + 1][row] = v.y;
            As[col + 2][row] = v.z; As[col + 3][row] = v.w;
        }
        #pragma unroll
        for (int it = 0; it < 2; ++it) {
            int f4   = tid + it * 256;
            int krow = f4 >> 5;
            int col  = (f4 & 31) << 2;
            int c    = bn + col;
            int k    = k0 + krow;
            float4 v = *reinterpret_cast<const float4*>(PW + (size_t)k * CDIM + c);
            *reinterpret_cast<float4*>(&Bs[krow][col]) = v;
        }
        __syncthreads();
        #pragma unroll
        for (int k = 0; k < 16; ++k) {
            float4 a0 = *reinterpret_cast<const float4*>(&As[k][tr * 8]);
            float4 a1 = *reinterpret_cast<const float4*>(&As[k][tr * 8 + 4]);
            float4 b0 = *reinterpret_cast<const float4*>(&Bs[k][tc * 8]);
            float4 b1 = *reinterpret_cast<const float4*>(&Bs[k][tc * 8 + 4]);
            float a[8] = {a0.x, a0.y, a0.z, a0.w, a1.x, a1.y, a1.z, a1.w};
            float b[8] = {b0.x, b0.y, b0.z, b0.w, b1.x, b1.y, b1.z, b1.w};
            #pragma unroll
            for (int i = 0; i < 8; ++i)
                #pragma unroll
                for (int j = 0; j < 8; ++j) acc[i][j] += a[i] * b[j];
        }
        __syncthreads();
    }
    // bias
    float4 bb0 = *reinterpret_cast<const float4*>(PB + bn + tc * 8);
    float4 bb1 = *reinterpret_cast<const float4*>(PB + bn + tc * 8 + 4);
    float bj[8] = {bb0.x, bb0.y, bb0.z, bb0.w, bb1.x, bb1.y, bb1.z, bb1.w};
    #pragma unroll
    for (int i = 0; i < 8; ++i) {
        int gr = bm + tr * 8 + i;
        if (gr >= N_NODES) continue;
        float r[8];
        #pragma unroll
        for (int j = 0; j < 8; ++j) {
            float v = acc[i][j] + bj[j];
            r[j] = (v > 0.0f) ? v : expm1f(v);
        }
        *reinterpret_cast<float4*>(out + (size_t)gr * CDIM + bn + tc * 8)
            = make_float4(r[0], r[1], r[2], r[3]);
        *reinterpret_cast<float4*>(out + (size_t)gr * CDIM + bn + tc * 8 + 4)
            = make_float4(r[4], r[5], r[6], r[7]);
    }
}

// ---------------- launch ------------------------------------------------------
extern "C" void kernel_launch(void* const* d_in, const int* in_sizes, int n_in,
                              void* d_out, int out_size) {
    const float* x      = (const float*)d_in[0];
    const int*   ei     = (const int*)d_in[1];     // jnp.int64 canonicalized -> int32
    const float* eattr  = (const float*)d_in[2];
    const float* W      = (const float*)d_in[3];
    const float* W_edge = (const float*)d_in[4];
    const float* att    = (const float*)d_in[5];
    const float* proj_w = (const float*)d_in[6];
    const float* proj_b = (const float*)d_in[7];
    float*       out    = (float*)d_out;

    long long ztotal = (long long)N_NODES * CDIM + (long long)N_NODES * NHEAD;
    int zblocks = (int)((ztotal + 255) / 256);
    k_zero<<<zblocks, 256>>>();

    k_w3<<<1, 64>>>(W_edge, att);

    dim3 g1((N_NODES + 127) / 128, CDIM / 128);
    k_gemm_xw<<<g1, 256>>>(x, W);

    k_s12<<<(N_NODES + 7) / 8, 256>>>(att);

    k_edgeA<<<(N_EDGES + 255) / 256, 256>>>(ei, eattr);

    k_edgeB<<<(N_EDGES + 7) / 8, 256>>>(ei);   // one warp per edge

    k_norm<<<((long long)N_NODES * CDIM + 255) / 256, 256>>>();

    k_gemm_out<<<g1, 256>>>(proj_w, proj_b, out);
}

// round 4
// speedup vs baseline: 2.6070x; 2.6070x over previous
#include <cuda_runtime.h>

#define N_NODES 100000
#define N_EDGES 1600000
#define NHEAD 4
#define HIDD 64
#define CDIM 256   // H*HID = IN_DIM = OUT_DIM
#define NEG_SLOPE 0.2f
#define SCAN_T 1024
#define SCAN_CHUNK ((N_NODES + SCAN_T - 1) / SCAN_T)   // 98

// ---------------- scratch (static device globals; no runtime allocation) ----
__device__ float  g_xw [ (size_t)N_NODES * CDIM ];   // x @ W
__device__ float  g_acc[ (size_t)N_NODES * CDIM ];   // normalized aggregated messages
__device__ float  g_s1 [ (size_t)N_NODES * NHEAD ];
__device__ float  g_s2 [ (size_t)N_NODES * NHEAD ];
__device__ float  g_w3 [ NHEAD * 16 ];
__device__ int    g_deg[ N_NODES ];
__device__ int    g_off[ N_NODES ];
__device__ int    g_cur[ N_NODES ];
__device__ float4 g_se [ N_EDGES ];                  // dst-sorted per-edge logits (4 heads)
__device__ int    g_ss [ N_EDGES ];                  // dst-sorted src index

// ---------------- zero degree counters --------------------------------------
__global__ void k_zero_deg() {
    int i = blockIdx.x * blockDim.x + threadIdx.x;
    if (i < N_NODES) g_deg[i] = 0;
}

// ---------------- w3[h][d] = sum_o W_edge[h][d][o] * a3[h][o] ---------------
__global__ void k_w3(const float* __restrict__ W_edge, const float* __restrict__ att) {
    int t = threadIdx.x;
    if (t >= NHEAD * 16) return;
    int h = t >> 4, d = t & 15;
    float s = 0.0f;
    #pragma unroll 8
    for (int o = 0; o < HIDD; ++o)
        s += W_edge[h * (16 * HIDD) + d * HIDD + o] * att[h * (3 * HIDD) + 2 * HIDD + o];
    g_w3[t] = s;
}

// ---------------- GEMM1: xw[n][h*64+o] = sum_i x[n][i] * W[h][i][o] ---------
__global__ __launch_bounds__(256) void k_gemm_xw(const float* __restrict__ X,
                                                 const float* __restrict__ W) {
    __shared__ float As[16][128];
    __shared__ float Bs[16][128];
    const int bm = blockIdx.x * 128;
    const int bn = blockIdx.y * 128;
    const int tid = threadIdx.x;
    const int tr = tid >> 4, tc = tid & 15;

    float acc[8][8];
    #pragma unroll
    for (int i = 0; i < 8; ++i)
        #pragma unroll
        for (int j = 0; j < 8; ++j) acc[i][j] = 0.0f;

    for (int k0 = 0; k0 < CDIM; k0 += 16) {
        #pragma unroll
        for (int it = 0; it < 2; ++it) {
            int f4  = tid + it * 256;
            int row = f4 >> 2;
            int col = (f4 & 3) << 2;
            int gr  = bm + row;
            float4 v = make_float4(0.f, 0.f, 0.f, 0.f);
            if (gr < N_NODES)
                v = *reinterpret_cast<const float4*>(X + (size_t)gr * CDIM + k0 + col);
            As[col + 0][row] = v.x; As[col + 1][row] = v.y;
            As[col + 2][row] = v.z; As[col + 3][row] = v.w;
        }
        #pragma unroll
        for (int it = 0; it < 2; ++it) {
            int f4   = tid + it * 256;
            int krow = f4 >> 5;
            int col  = (f4 & 31) << 2;
            int c    = bn + col;
            int k    = k0 + krow;
            float4 v = *reinterpret_cast<const float4*>(
                W + (size_t)(c >> 6) * (CDIM * HIDD) + (size_t)k * HIDD + (c & 63));
            *reinterpret_cast<float4*>(&Bs[krow][col]) = v;
        }
        __syncthreads();
        #pragma unroll
        for (int k = 0; k < 16; ++k) {
            float4 a0 = *reinterpret_cast<const float4*>(&As[k][tr * 8]);
            float4 a1 = *reinterpret_cast<const float4*>(&As[k][tr * 8 + 4]);
            float4 b0 = *reinterpret_cast<const float4*>(&Bs[k][tc * 8]);
            float4 b1 = *reinterpret_cast<const float4*>(&Bs[k][tc * 8 + 4]);
            float a[8] = {a0.x, a0.y, a0.z, a0.w, a1.x, a1.y, a1.z, a1.w};
            float b[8] = {b0.x, b0.y, b0.z, b0.w, b1.x, b1.y, b1.z, b1.w};
            #pragma unroll
            for (int i = 0; i < 8; ++i)
                #pragma unroll
                for (int j = 0; j < 8; ++j) acc[i][j] += a[i] * b[j];
        }
        __syncthreads();
    }
    #pragma unroll
    for (int i = 0; i < 8; ++i) {
        int gr = bm + tr * 8 + i;
        if (gr >= N_NODES) continue;
        float4 v0 = make_float4(acc[i][0], acc[i][1], acc[i][2], acc[i][3]);
        float4 v1 = make_float4(acc[i][4], acc[i][5], acc[i][6], acc[i][7]);
        *reinterpret_cast<float4*>(g_xw + (size_t)gr * CDIM + bn + tc * 8)     = v0;
        *reinterpret_cast<float4*>(g_xw + (size_t)gr * CDIM + bn + tc * 8 + 4) = v1;
    }
}

// ---------------- s1/s2: per-node dot of xw with a1/a2 (warp per node) -----
__global__ __launch_bounds__(256) void k_s12(const float* __restrict__ att) {
    __shared__ float a1s[CDIM];
    __shared__ float a2s[CDIM];
    int tid = threadIdx.x;
    {
        int h = tid >> 6, o = tid & 63;
        a1s[tid] = att[h * (3 * HIDD) + o];
        a2s[tid] = att[h * (3 * HIDD) + HIDD + o];
    }
    __syncthreads();
    int warp = tid >> 5, lane = tid & 31;
    long long n = (long long)blockIdx.x * 8 + warp;
    if (n >= N_NODES) return;
    const float4* xp = reinterpret_cast<const float4*>(g_xw + n * CDIM + lane * 8);
    float4 v0 = xp[0], v1 = xp[1];
    int base = lane * 8;
    float p1 = v0.x * a1s[base]     + v0.y * a1s[base + 1] + v0.z * a1s[base + 2] + v0.w * a1s[base + 3]
             + v1.x * a1s[base + 4] + v1.y * a1s[base + 5] + v1.z * a1s[base + 6] + v1.w * a1s[base + 7];
    float p2 = v0.x * a2s[base]     + v0.y * a2s[base + 1] + v0.z * a2s[base + 2] + v0.w * a2s[base + 3]
             + v1.x * a2s[base + 4] + v1.y * a2s[base + 5] + v1.z * a2s[base + 6] + v1.w * a2s[base + 7];
    #pragma unroll
    for (int off = 4; off; off >>= 1) {
        p1 += __shfl_down_sync(0xffffffffu, p1, off, 8);
        p2 += __shfl_down_sync(0xffffffffu, p2, off, 8);
    }
    if ((lane & 7) == 0) {
        int h = lane >> 3;
        g_s1[n * NHEAD + h] = p1;
        g_s2[n * NHEAD + h] = p2;
    }
}

// ---------------- degree histogram -------------------------------------------
__global__ __launch_bounds__(256) void k_deg(const int* __restrict__ ei) {
    long long id = (long long)blockIdx.x * 256 + threadIdx.x;
    if (id >= N_EDGES) return;
    atomicAdd(&g_deg[ei[(long long)N_EDGES + id]], 1);
}

// ---------------- single-block exclusive scan of degrees ---------------------
__global__ __launch_bounds__(SCAN_T) void k_scan() {
    __shared__ int s[SCAN_T];
    int t = threadIdx.x;
    int start = t * SCAN_CHUNK;
    int end = min(start + SCAN_CHUNK, N_NODES);
    int local = 0;
    for (int i = start; i < end; ++i) local += g_deg[i];
    s[t] = local;
    __syncthreads();
    // Hillis-Steele inclusive scan
    for (int off = 1; off < SCAN_T; off <<= 1) {
        int v = (t >= off) ? s[t - off] : 0;
        __syncthreads();
        s[t] += v;
        __syncthreads();
    }
    int run = s[t] - local;   // exclusive prefix of this chunk
    for (int i = start; i < end; ++i) {
        g_off[i] = run;
        g_cur[i] = run;
        run += g_deg[i];
    }
}

// ---------------- edge scatter: compute logits, write dst-sorted -------------
__global__ __launch_bounds__(256) void k_scatter(const int* __restrict__ ei,
                                                 const float* __restrict__ eattr) {
    __shared__ float w3s[NHEAD * 16];
    if (threadIdx.x < NHEAD * 16) w3s[threadIdx.x] = g_w3[threadIdx.x];
    __syncthreads();
    long long id = (long long)blockIdx.x * 256 + threadIdx.x;
    if (id >= N_EDGES) return;
    int src = ei[id];
    int dst = ei[(long long)N_EDGES + id];
    const float4* ap = reinterpret_cast<const float4*>(eattr + id * 16);
    float4 e0 = ap[0], e1 = ap[1], e2 = ap[2], e3 = ap[3];
    float attr[16] = {e0.x, e0.y, e0.z, e0.w, e1.x, e1.y, e1.z, e1.w,
                      e2.x, e2.y, e2.z, e2.w, e3.x, e3.y, e3.z, e3.w};
    float4 s1v = *reinterpret_cast<const float4*>(g_s1 + (size_t)dst * NHEAD);
    float4 s2v = *reinterpret_cast<const float4*>(g_s2 + (size_t)src * NHEAD);
    float eh[NHEAD];
    #pragma unroll
    for (int h = 0; h < NHEAD; ++h) {
        float d = 0.0f;
        #pragma unroll
        for (int q = 0; q < 16; ++q) d += attr[q] * w3s[h * 16 + q];
        eh[h] = d;
    }
    eh[0] += s1v.x + s2v.x; eh[1] += s1v.y + s2v.y;
    eh[2] += s1v.z + s2v.z; eh[3] += s1v.w + s2v.w;
    #pragma unroll
    for (int h = 0; h < NHEAD; ++h)
        eh[h] = (eh[h] >= 0.0f) ? eh[h] : NEG_SLOPE * eh[h];
    int pos = atomicAdd(&g_cur[dst], 1);
    g_se[pos] = make_float4(eh[0], eh[1], eh[2], eh[3]);
    g_ss[pos] = src;
}

// ---------------- aggregation: warp per node, no atomics ---------------------
// lane l handles cols [l*8, l*8+8); head = l>>3
__global__ __launch_bounds__(256) void k_agg() {
    int warp = threadIdx.x >> 5, lane = threadIdx.x & 31;
    int n = blockIdx.x * 8 + warp;
    if (n >= N_NODES) return;
    int base = g_off[n];
    int deg  = g_deg[n];
    int h    = lane >> 3;

    // pass 1: per-head max (lane-strided, then warp reduce)
    float4 mx = make_float4(-3.0e38f, -3.0e38f, -3.0e38f, -3.0e38f);
    for (int i = lane; i < deg; i += 32) {
        float4 ev = g_se[base + i];
        mx.x = fmaxf(mx.x, ev.x); mx.y = fmaxf(mx.y, ev.y);
        mx.z = fmaxf(mx.z, ev.z); mx.w = fmaxf(mx.w, ev.w);
    }
    #pragma unroll
    for (int off = 16; off; off >>= 1) {
        mx.x = fmaxf(mx.x, __shfl_xor_sync(0xffffffffu, mx.x, off));
        mx.y = fmaxf(mx.y, __shfl_xor_sync(0xffffffffu, mx.y, off));
        mx.z = fmaxf(mx.z, __shfl_xor_sync(0xffffffffu, mx.z, off));
        mx.w = fmaxf(mx.w, __shfl_xor_sync(0xffffffffu, mx.w, off));
    }
    float m_h = (h == 0) ? mx.x : (h == 1) ? mx.y : (h == 2) ? mx.z : mx.w;

    // pass 2: exp + sum + weighted accumulate (registers, no atomics)
    float a0x = 0.f, a0y = 0.f, a0z = 0.f, a0w = 0.f;
    float a1x = 0.f, a1y = 0.f, a1z = 0.f, a1w = 0.f;
    float sum = 0.f;
    int col = lane * 8;

    float4 ev_n = make_float4(0.f, 0.f, 0.f, 0.f);
    int src_n = 0;
    if (deg > 0) { ev_n = g_se[base]; src_n = g_ss[base]; }
    for (int i = 0; i < deg; ++i) {
        float4 ev = ev_n;
        int src = src_n;
        if (i + 1 < deg) { ev_n = g_se[base + i + 1]; src_n = g_ss[base + i + 1]; }
        float e_h = (h == 0) ? ev.x : (h == 1) ? ev.y : (h == 2) ? ev.z : ev.w;
        float ex = __expf(e_h - m_h);
        sum += ex;
        const float4* xp = reinterpret_cast<const float4*>(g_xw + (size_t)src * CDIM + col);
        float4 v0 = xp[0], v1 = xp[1];
        a0x += v0.x * ex; a0y += v0.y * ex; a0z += v0.z * ex; a0w += v0.w * ex;
        a1x += v1.x * ex; a1y += v1.y * ex; a1z += v1.z * ex; a1w += v1.w * ex;
    }
    float inv = 1.0f / (sum + 1e-16f);
    float* dp = g_acc + (size_t)n * CDIM + col;
    *reinterpret_cast<float4*>(dp)     = make_float4(a0x * inv, a0y * inv, a0z * inv, a0w * inv);
    *reinterpret_cast<float4*>(dp + 4) = make_float4(a1x * inv, a1y * inv, a1z * inv, a1w * inv);
}

// ---------------- GEMM2: out = elu(acc @ proj_w + b) -------------------------
__global__ __launch_bounds__(256) void k_gemm_out(const float* __restrict__ PW,
                                                  const float* __restrict__ PB,
                                                  float* __restrict__ out) {
    __shared__ float As[16][128];
    __shared__ float Bs[16][128];
    const int bm = blockIdx.x * 128;
    const int bn = blockIdx.y * 128;
    const int tid = threadIdx.x;
    const int tr = tid >> 4, tc = tid & 15;

    float acc[8][8];
    #pragma unroll
    for (int i = 0; i < 8; ++i)
        #pragma unroll
        for (int j = 0; j < 8; ++j) acc[i][j] = 0.0f;

    for (int k0 = 0; k0 < CDIM; k0 += 16) {
        #pragma unroll
        for (int it = 0; it < 2; ++it) {
            int f4  = tid + it * 256;
            int row = f4 >> 2;
            int col = (f4 & 3) << 2;
            int gr  = bm + row;
            float4 v = make_float4(0.f, 0.f, 0.f, 0.f);
            if (gr < N_NODES)
                v = *reinterpret_cast<const float4*>(g_acc + (size_t)gr * CDIM + k0 + col);
            As[col + 0][row] = v.x; As[col + 1][row] = v.y;
            As[col + 2][row] = v.z; As[col + 3][row] = v.w;
        }
        #pragma unroll
        for (int it = 0; it < 2; ++it) {
            int f4   = tid + it * 256;
            int krow = f4 >> 5;
            int col  = (f4 & 31) << 2;
            int c    = bn + col;
            int k    = k0 + krow;
            float4 v = *reinterpret_cast<const float4*>(PW + (size_t)k * CDIM + c);
            *reinterpret_cast<float4*>(&Bs[krow][col]) = v;
        }
        __syncthreads();
        #pragma unroll
        for (int k = 0; k < 16; ++k) {
            float4 a0 = *reinterpret_cast<const float4*>(&As[k][tr * 8]);
            float4 a1 = *reinterpret_cast<const float4*>(&As[k][tr * 8 + 4]);
            float4 b0 = *reinterpret_cast<const float4*>(&Bs[k][tc * 8]);
            float4 b1 = *reinterpret_cast<const float4*>(&Bs[k][tc * 8 + 4]);
            float a[8] = {a0.x, a0.y, a0.z, a0.w, a1.x, a1.y, a1.z, a1.w};
            float b[8] = {b0.x, b0.y, b0.z, b0.w, b1.x, b1.y, b1.z, b1.w};
            #pragma unroll
            for (int i = 0; i < 8; ++i)
                #pragma unroll
                for (int j = 0; j < 8; ++j) acc[i][j] += a[i] * b[j];
        }
        __syncthreads();
    }
    float4 bb0 = *reinterpret_cast<const float4*>(PB + bn + tc * 8);
    float4 bb1 = *reinterpret_cast<const float4*>(PB + bn + tc * 8 + 4);
    float bj[8] = {bb0.x, bb0.y, bb0.z, bb0.w, bb1.x, bb1.y, bb1.z, bb1.w};
    #pragma unroll
    for (int i = 0; i < 8; ++i) {
        int gr = bm + tr * 8 + i;
        if (gr >= N_NODES) continue;
        float r[8];
        #pragma unroll
        for (int j = 0; j < 8; ++j) {
            float v = acc[i][j] + bj[j];
            r[j] = (v > 0.0f) ? v : expm1f(v);
        }
        *reinterpret_cast<float4*>(out + (size_t)gr * CDIM + bn + tc * 8)
            = make_float4(r[0], r[1], r[2], r[3]);
        *reinterpret_cast<float4*>(out + (size_t)gr * CDIM + bn + tc * 8 + 4)
            = make_float4(r[4], r[5], r[6], r[7]);
    }
}

// ---------------- launch ------------------------------------------------------
extern "C" void kernel_launch(void* const* d_in, const int* in_sizes, int n_in,
                              void* d_out, int out_size) {
    const float* x      = (const float*)d_in[0];
    const int*   ei     = (const int*)d_in[1];     // int32 (JAX x64 disabled)
    const float* eattr  = (const float*)d_in[2];
    const float* W      = (const float*)d_in[3];
    const float* W_edge = (const float*)d_in[4];
    const float* att    = (const float*)d_in[5];
    const float* proj_w = (const float*)d_in[6];
    const float* proj_b = (const float*)d_in[7];
    float*       out    = (float*)d_out;

    k_zero_deg<<<(N_NODES + 255) / 256, 256>>>();
    k_w3<<<1, 64>>>(W_edge, att);

    dim3 g1((N_NODES + 127) / 128, CDIM / 128);
    k_gemm_xw<<<g1, 256>>>(x, W);

    k_s12<<<(N_NODES + 7) / 8, 256>>>(att);

    k_deg<<<(N_EDGES + 255) / 256, 256>>>(ei);
    k_scan<<<1, SCAN_T>>>();
    k_scatter<<<(N_EDGES + 255) / 256, 256>>>(ei, eattr);

    k_agg<<<(N_NODES + 7) / 8, 256>>>();

    k_gemm_out<<<g1, 256>>>(proj_w, proj_b, out);
}

// round 9
// speedup vs baseline: 2.6532x; 1.0177x over previous
#include <cuda_runtime.h>

#define N_NODES 100000
#define N_EDGES 1600000
#define NHEAD 4
#define HIDD 64
#define CDIM 256   // H*HID = IN_DIM = OUT_DIM
#define NEG_SLOPE 0.2f
#define SCAN_T 1024
#define SCAN_CHUNK ((N_NODES + SCAN_T - 1) / SCAN_T)   // 98

// ---------------- scratch (static device globals; no runtime allocation) ----
__device__ float  g_xw [ (size_t)N_NODES * CDIM ];
__device__ float  g_acc[ (size_t)N_NODES * CDIM ];
__device__ float  g_s1 [ (size_t)N_NODES * NHEAD ];
__device__ float  g_s2 [ (size_t)N_NODES * NHEAD ];
__device__ float  g_w3 [ NHEAD * 16 ];
__device__ int    g_deg[ N_NODES ];
__device__ int    g_off[ N_NODES ];
__device__ int    g_cur[ N_NODES ];
__device__ float4 g_se [ N_EDGES ];
__device__ int    g_ss [ N_EDGES ];

// ---------------- zero degree counters --------------------------------------
__global__ void k_zero_deg() {
    int i = blockIdx.x * blockDim.x + threadIdx.x;
    if (i < N_NODES) g_deg[i] = 0;
}

// ---------------- w3[h][d] = sum_o W_edge[h][d][o] * a3[h][o] ---------------
__global__ void k_w3(const float* __restrict__ W_edge, const float* __restrict__ att) {
    int t = threadIdx.x;
    if (t >= NHEAD * 16) return;
    int h = t >> 4, d = t & 15;
    float s = 0.0f;
    #pragma unroll 8
    for (int o = 0; o < HIDD; ++o)
        s += W_edge[h * (16 * HIDD) + d * HIDD + o] * att[h * (3 * HIDD) + 2 * HIDD + o];
    g_w3[t] = s;
}

// ---------------- GEMM1: xw[n][h*64+o] = sum_i x[n][i] * W[h][i][o] ---------
// (R4-proven SIMT version: 128x128 tile, BK=16, 256 threads, 8x8 reg tile)
__global__ __launch_bounds__(256) void k_gemm_xw(const float* __restrict__ X,
                                                 const float* __restrict__ W) {
    __shared__ float As[16][128];
    __shared__ float Bs[16][128];
    const int bm = blockIdx.x * 128;
    const int bn = blockIdx.y * 128;
    const int tid = threadIdx.x;
    const int tr = tid >> 4, tc = tid & 15;

    float acc[8][8];
    #pragma unroll
    for (int i = 0; i < 8; ++i)
        #pragma unroll
        for (int j = 0; j < 8; ++j) acc[i][j] = 0.0f;

    for (int k0 = 0; k0 < CDIM; k0 += 16) {
        #pragma unroll
        for (int it = 0; it < 2; ++it) {
            int f4  = tid + it * 256;
            int row = f4 >> 2;
            int col = (f4 & 3) << 2;
            int gr  = bm + row;
            float4 v = make_float4(0.f, 0.f, 0.f, 0.f);
            if (gr < N_NODES)
                v = *reinterpret_cast<const float4*>(X + (size_t)gr * CDIM + k0 + col);
            As[col + 0][row] = v.x; As[col + 1][row] = v.y;
            As[col + 2][row] = v.z; As[col + 3][row] = v.w;
        }
        #pragma unroll
        for (int it = 0; it < 2; ++it) {
            int f4   = tid + it * 256;
            int krow = f4 >> 5;
            int col  = (f4 & 31) << 2;
            int c    = bn + col;
            int k    = k0 + krow;
            float4 v = *reinterpret_cast<const float4*>(
                W + (size_t)(c >> 6) * (CDIM * HIDD) + (size_t)k * HIDD + (c & 63));
            *reinterpret_cast<float4*>(&Bs[krow][col]) = v;
        }
        __syncthreads();
        #pragma unroll
        for (int k = 0; k < 16; ++k) {
            float4 a0 = *reinterpret_cast<const float4*>(&As[k][tr * 8]);
            float4 a1 = *reinterpret_cast<const float4*>(&As[k][tr * 8 + 4]);
            float4 b0 = *reinterpret_cast<const float4*>(&Bs[k][tc * 8]);
            float4 b1 = *reinterpret_cast<const float4*>(&Bs[k][tc * 8 + 4]);
            float a[8] = {a0.x, a0.y, a0.z, a0.w, a1.x, a1.y, a1.z, a1.w};
            float b[8] = {b0.x, b0.y, b0.z, b0.w, b1.x, b1.y, b1.z, b1.w};
            #pragma unroll
            for (int i = 0; i < 8; ++i)
                #pragma unroll
                for (int j = 0; j < 8; ++j) acc[i][j] += a[i] * b[j];
        }
        __syncthreads();
    }
    #pragma unroll
    for (int i = 0; i < 8; ++i) {
        int gr = bm + tr * 8 + i;
        if (gr >= N_NODES) continue;
        float4 v0 = make_float4(acc[i][0], acc[i][1], acc[i][2], acc[i][3]);
        float4 v1 = make_float4(acc[i][4], acc[i][5], acc[i][6], acc[i][7]);
        *reinterpret_cast<float4*>(g_xw + (size_t)gr * CDIM + bn + tc * 8)     = v0;
        *reinterpret_cast<float4*>(g_xw + (size_t)gr * CDIM + bn + tc * 8 + 4) = v1;
    }
}

// ---------------- s1/s2: per-node dot of xw with a1/a2 (warp per node) -----
__global__ __launch_bounds__(256) void k_s12(const float* __restrict__ att) {
    __shared__ float a1s[CDIM];
    __shared__ float a2s[CDIM];
    int tid = threadIdx.x;
    {
        int h = tid >> 6, o = tid & 63;
        a1s[tid] = att[h * (3 * HIDD) + o];
        a2s[tid] = att[h * (3 * HIDD) + HIDD + o];
    }
    __syncthreads();
    int warp = tid >> 5, lane = tid & 31;
    long long n = (long long)blockIdx.x * 8 + warp;
    if (n >= N_NODES) return;
    const float4* xp = reinterpret_cast<const float4*>(g_xw + n * CDIM + lane * 8);
    float4 v0 = xp[0], v1 = xp[1];
    int base = lane * 8;
    float p1 = v0.x * a1s[base]     + v0.y * a1s[base + 1] + v0.z * a1s[base + 2] + v0.w * a1s[base + 3]
             + v1.x * a1s[base + 4] + v1.y * a1s[base + 5] + v1.z * a1s[base + 6] + v1.w * a1s[base + 7];
    float p2 = v0.x * a2s[base]     + v0.y * a2s[base + 1] + v0.z * a2s[base + 2] + v0.w * a2s[base + 3]
             + v1.x * a2s[base + 4] + v1.y * a2s[base + 5] + v1.z * a2s[base + 6] + v1.w * a2s[base + 7];
    #pragma unroll
    for (int off = 4; off; off >>= 1) {
        p1 += __shfl_down_sync(0xffffffffu, p1, off, 8);
        p2 += __shfl_down_sync(0xffffffffu, p2, off, 8);
    }
    if ((lane & 7) == 0) {
        int h = lane >> 3;
        g_s1[n * NHEAD + h] = p1;
        g_s2[n * NHEAD + h] = p2;
    }
}

// ---------------- degree histogram -------------------------------------------
__global__ __launch_bounds__(256) void k_deg(const int* __restrict__ ei) {
    long long id = (long long)blockIdx.x * 256 + threadIdx.x;
    if (id >= N_EDGES) return;
    atomicAdd(&g_deg[ei[(long long)N_EDGES + id]], 1);
}

// ---------------- single-block exclusive scan of degrees ---------------------
__global__ __launch_bounds__(SCAN_T) void k_scan() {
    __shared__ int s[SCAN_T];
    int t = threadIdx.x;
    int start = t * SCAN_CHUNK;
    int end = min(start + SCAN_CHUNK, N_NODES);
    int local = 0;
    for (int i = start; i < end; ++i) local += g_deg[i];
    s[t] = local;
    __syncthreads();
    for (int off = 1; off < SCAN_T; off <<= 1) {
        int v = (t >= off) ? s[t - off] : 0;
        __syncthreads();
        s[t] += v;
        __syncthreads();
    }
    int run = s[t] - local;
    for (int i = start; i < end; ++i) {
        g_off[i] = run;
        g_cur[i] = run;
        run += g_deg[i];
    }
}

// ---------------- edge scatter: compute logits, write dst-sorted -------------
__global__ __launch_bounds__(256) void k_scatter(const int* __restrict__ ei,
                                                 const float* __restrict__ eattr) {
    __shared__ float w3s[NHEAD * 16];
    if (threadIdx.x < NHEAD * 16) w3s[threadIdx.x] = g_w3[threadIdx.x];
    __syncthreads();
    long long id = (long long)blockIdx.x * 256 + threadIdx.x;
    if (id >= N_EDGES) return;
    int src = ei[id];
    int dst = ei[(long long)N_EDGES + id];
    const float4* ap = reinterpret_cast<const float4*>(eattr + id * 16);
    float4 e0 = ap[0], e1 = ap[1], e2 = ap[2], e3 = ap[3];
    float attr[16] = {e0.x, e0.y, e0.z, e0.w, e1.x, e1.y, e1.z, e1.w,
                      e2.x, e2.y, e2.z, e2.w, e3.x, e3.y, e3.z, e3.w};
    float4 s1v = *reinterpret_cast<const float4*>(g_s1 + (size_t)dst * NHEAD);
    float4 s2v = *reinterpret_cast<const float4*>(g_s2 + (size_t)src * NHEAD);
    float eh[NHEAD];
    #pragma unroll
    for (int h = 0; h < NHEAD; ++h) {
        float d = 0.0f;
        #pragma unroll
        for (int q = 0; q < 16; ++q) d += attr[q] * w3s[h * 16 + q];
        eh[h] = d;
    }
    eh[0] += s1v.x + s2v.x; eh[1] += s1v.y + s2v.y;
    eh[2] += s1v.z + s2v.z; eh[3] += s1v.w + s2v.w;
    #pragma unroll
    for (int h = 0; h < NHEAD; ++h)
        eh[h] = (eh[h] >= 0.0f) ? eh[h] : NEG_SLOPE * eh[h];
    int pos = atomicAdd(&g_cur[dst], 1);
    g_se[pos] = make_float4(eh[0], eh[1], eh[2], eh[3]);
    g_ss[pos] = src;
}

// ---------------- aggregation: warp per node, no atomics, unroll x2 ----------
// lane l handles cols [l*8, l*8+8); head = l>>3
__global__ __launch_bounds__(256) void k_agg() {
    int warp = threadIdx.x >> 5, lane = threadIdx.x & 31;
    int n = blockIdx.x * 8 + warp;
    if (n >= N_NODES) return;
    int base = g_off[n];
    int deg  = g_deg[n];
    int h    = lane >> 3;
    int col  = lane * 8;

    // pass 1: per-head max
    float4 mx = make_float4(-3.0e38f, -3.0e38f, -3.0e38f, -3.0e38f);
    for (int i = lane; i < deg; i += 32) {
        float4 ev = g_se[base + i];
        mx.x = fmaxf(mx.x, ev.x); mx.y = fmaxf(mx.y, ev.y);
        mx.z = fmaxf(mx.z, ev.z); mx.w = fmaxf(mx.w, ev.w);
    }
    #pragma unroll
    for (int off = 16; off; off >>= 1) {
        mx.x = fmaxf(mx.x, __shfl_xor_sync(0xffffffffu, mx.x, off));
        mx.y = fmaxf(mx.y, __shfl_xor_sync(0xffffffffu, mx.y, off));
        mx.z = fmaxf(mx.z, __shfl_xor_sync(0xffffffffu, mx.z, off));
        mx.w = fmaxf(mx.w, __shfl_xor_sync(0xffffffffu, mx.w, off));
    }
    float m_h = (h == 0) ? mx.x : (h == 1) ? mx.y : (h == 2) ? mx.z : mx.w;

    // pass 2: exp + sum + weighted accumulate, two independent edges per iter
    float a0x = 0.f, a0y = 0.f, a0z = 0.f, a0w = 0.f;
    float a1x = 0.f, a1y = 0.f, a1z = 0.f, a1w = 0.f;
    float sum = 0.f;

    int i = 0;
    for (; i + 2 <= deg; i += 2) {
        float4 evA = __ldg(&g_se[base + i]);
        float4 evB = __ldg(&g_se[base + i + 1]);
        int srcA = __ldg(&g_ss[base + i]);
        int srcB = __ldg(&g_ss[base + i + 1]);
        float eA = (h == 0) ? evA.x : (h == 1) ? evA.y : (h == 2) ? evA.z : evA.w;
        float eB = (h == 0) ? evB.x : (h == 1) ? evB.y : (h == 2) ? evB.z : evB.w;
        float exA = __expf(eA - m_h);
        float exB = __expf(eB - m_h);
        sum += exA + exB;
        const float4* xpA = reinterpret_cast<const float4*>(g_xw + (size_t)srcA * CDIM + col);
        const float4* xpB = reinterpret_cast<const float4*>(g_xw + (size_t)srcB * CDIM + col);
        float4 vA0 = __ldg(xpA), vA1 = __ldg(xpA + 1);
        float4 vB0 = __ldg(xpB), vB1 = __ldg(xpB + 1);
        a0x += vA0.x * exA; a0y += vA0.y * exA; a0z += vA0.z * exA; a0w += vA0.w * exA;
        a1x += vA1.x * exA; a1y += vA1.y * exA; a1z += vA1.z * exA; a1w += vA1.w * exA;
        a0x += vB0.x * exB; a0y += vB0.y * exB; a0z += vB0.z * exB; a0w += vB0.w * exB;
        a1x += vB1.x * exB; a1y += vB1.y * exB; a1z += vB1.z * exB; a1w += vB1.w * exB;
    }
    if (i < deg) {
        float4 ev = __ldg(&g_se[base + i]);
        int src = __ldg(&g_ss[base + i]);
        float e_h = (h == 0) ? ev.x : (h == 1) ? ev.y : (h == 2) ? ev.z : ev.w;
        float ex = __expf(e_h - m_h);
        sum += ex;
        const float4* xp = reinterpret_cast<const float4*>(g_xw + (size_t)src * CDIM + col);
        float4 v0 = __ldg(xp), v1 = __ldg(xp + 1);
        a0x += v0.x * ex; a0y += v0.y * ex; a0z += v0.z * ex; a0w += v0.w * ex;
        a1x += v1.x * ex; a1y += v1.y * ex; a1z += v1.z * ex; a1w += v1.w * ex;
    }
    float inv = 1.0f / (sum + 1e-16f);
    float* dp = g_acc + (size_t)n * CDIM + col;
    *reinterpret_cast<float4*>(dp)     = make_float4(a0x * inv, a0y * inv, a0z * inv, a0w * inv);
    *reinterpret_cast<float4*>(dp + 4) = make_float4(a1x * inv, a1y * inv, a1z * inv, a1w * inv);
}

// ---------------- GEMM2: out = elu(acc @ proj_w + b) (R4-proven SIMT) --------
__global__ __launch_bounds__(256) void k_gemm_out(const float* __restrict__ PW,
                                                  const float* __restrict__ PB,
                                                  float* __restrict__ out) {
    __shared__ float As[16][128];
    __shared__ float Bs[16][128];
    const int bm = blockIdx.x * 128;
    const int bn = blockIdx.y * 128;
    const int tid = threadIdx.x;
    const int tr = tid >> 4, tc = tid & 15;

    float acc[8][8];
    #pragma unroll
    for (int i = 0; i < 8; ++i)
        #pragma unroll
        for (int j = 0; j < 8; ++j) acc[i][j] = 0.0f;

    for (int k0 = 0; k0 < CDIM; k0 += 16) {
        #pragma unroll
        for (int it = 0; it < 2; ++it) {
            int f4  = tid + it * 256;
            int row = f4 >> 2;
            int col = (f4 & 3) << 2;
            int gr  = bm + row;
            float4 v = make_float4(0.f, 0.f, 0.f, 0.f);
            if (gr < N_NODES)
                v = *reinterpret_cast<const float4*>(g_acc + (size_t)gr * CDIM + k0 + col);
            As[col + 0][row] = v.x; As[col + 1][row] = v.y;
            As[col + 2][row] = v.z; As[col + 3][row] = v.w;
        }
        #pragma unroll
        for (int it = 0; it < 2; ++it) {
            int f4   = tid + it * 256;
            int krow = f4 >> 5;
            int col  = (f4 & 31) << 2;
            int c    = bn + col;
            int k    = k0 + krow;
            float4 v = *reinterpret_cast<const float4*>(PW + (size_t)k * CDIM + c);
            *reinterpret_cast<float4*>(&Bs[krow][col]) = v;
        }
        __syncthreads();
        #pragma unroll
        for (int k = 0; k < 16; ++k) {
            float4 a0 = *reinterpret_cast<const float4*>(&As[k][tr * 8]);
            float4 a1 = *reinterpret_cast<const float4*>(&As[k][tr * 8 + 4]);
            float4 b0 = *reinterpret_cast<const float4*>(&Bs[k][tc * 8]);
            float4 b1 = *reinterpret_cast<const float4*>(&Bs[k][tc * 8 + 4]);
            float a[8] = {a0.x, a0.y, a0.z, a0.w, a1.x, a1.y, a1.z, a1.w};
            float b[8] = {b0.x, b0.y, b0.z, b0.w, b1.x, b1.y, b1.z, b1.w};
            #pragma unroll
            for (int i = 0; i < 8; ++i)
                #pragma unroll
                for (int j = 0; j < 8; ++j) acc[i][j] += a[i] * b[j];
        }
        __syncthreads();
    }
    float4 bb0 = *reinterpret_cast<const float4*>(PB + bn + tc * 8);
    float4 bb1 = *reinterpret_cast<const float4*>(PB + bn + tc * 8 + 4);
    float bj[8] = {bb0.x, bb0.y, bb0.z, bb0.w, bb1.x, bb1.y, bb1.z, bb1.w};
    #pragma unroll
    for (int i = 0; i < 8; ++i) {
        int gr = bm + tr * 8 + i;
        if (gr >= N_NODES) continue;
        float r[8];
        #pragma unroll
        for (int j = 0; j < 8; ++j) {
            float v = acc[i][j] + bj[j];
            r[j] = (v > 0.0f) ? v : expm1f(v);
        }
        *reinterpret_cast<float4*>(out + (size_t)gr * CDIM + bn + tc * 8)
            = make_float4(r[0], r[1], r[2], r[3]);
        *reinterpret_cast<float4*>(out + (size_t)gr * CDIM + bn + tc * 8 + 4)
            = make_float4(r[4], r[5], r[6], r[7]);
    }
}

// ---------------- launch ------------------------------------------------------
extern "C" void kernel_launch(void* const* d_in, const int* in_sizes, int n_in,
                              void* d_out, int out_size) {
    const float* x      = (const float*)d_in[0];
    const int*   ei     = (const int*)d_in[1];
    const float* eattr  = (const float*)d_in[2];
    const float* W      = (const float*)d_in[3];
    const float* W_edge = (const float*)d_in[4];
    const float* att    = (const float*)d_in[5];
    const float* proj_w = (const float*)d_in[6];
    const float* proj_b = (const float*)d_in[7];
    float*       out    = (float*)d_out;

    k_zero_deg<<<(N_NODES + 255) / 256, 256>>>();
    k_w3<<<1, 64>>>(W_edge, att);

    dim3 g1((N_NODES + 127) / 128, CDIM / 128);
    k_gemm_xw<<<g1, 256>>>(x, W);

    k_s12<<<(N_NODES + 7) / 8, 256>>>(att);

    k_deg<<<(N_EDGES + 255) / 256, 256>>>(ei);
    k_scan<<<1, SCAN_T>>>();
    k_scatter<<<(N_EDGES + 255) / 256, 256>>>(ei, eattr);

    k_agg<<<(N_NODES + 7) / 8, 256>>>();

    k_gemm_out<<<g1, 256>>>(proj_w, proj_b, out);
}

// round 10
// speedup vs baseline: 2.8322x; 1.0674x over previous
#include <cuda_runtime.h>

#define N_NODES 100000
#define N_EDGES 1600000
#define NHEAD 4
#define HIDD 64
#define CDIM 256   // H*HID = IN_DIM = OUT_DIM
#define NEG_SLOPE 0.2f
#define SCAN_T 1024
#define SCAN_CHUNK ((N_NODES + SCAN_T - 1) / SCAN_T)   // 98

typedef unsigned long long u64;

// ---------------- scratch (static device globals; no runtime allocation) ----
__device__ float  g_xw [ (size_t)N_NODES * CDIM ];
__device__ float  g_acc[ (size_t)N_NODES * CDIM ];
__device__ float  g_s1 [ (size_t)N_NODES * NHEAD ];
__device__ float  g_s2 [ (size_t)N_NODES * NHEAD ];
__device__ float  g_w3 [ NHEAD * 16 ];
__device__ int    g_deg[ N_NODES ];
__device__ int    g_off[ N_NODES ];
__device__ int    g_cur[ N_NODES ];
__device__ float4 g_se [ N_EDGES ];
__device__ int    g_ss [ N_EDGES ];

// ---------------- packed f32x2 helpers (sm_100+) -----------------------------
__device__ __forceinline__ void ffma2(u64& d, u64 a, u64 b) {
    asm("fma.rn.f32x2 %0, %1, %2, %0;" : "+l"(d) : "l"(a), "l"(b));
}
__device__ __forceinline__ u64 pack2(float lo, float hi) {
    u64 r; asm("mov.b64 %0, {%1, %2};" : "=l"(r) : "f"(lo), "f"(hi)); return r;
}
__device__ __forceinline__ void unpack2(u64 v, float& lo, float& hi) {
    asm("mov.b64 {%0, %1}, %2;" : "=f"(lo), "=f"(hi) : "l"(v));
}

// ---------------- zero degree counters --------------------------------------
__global__ void k_zero_deg() {
    int i = blockIdx.x * blockDim.x + threadIdx.x;
    if (i < N_NODES) g_deg[i] = 0;
}

// ---------------- w3[h][d] = sum_o W_edge[h][d][o] * a3[h][o] ---------------
__global__ void k_w3(const float* __restrict__ W_edge, const float* __restrict__ att) {
    int t = threadIdx.x;
    if (t >= NHEAD * 16) return;
    int h = t >> 4, d = t & 15;
    float s = 0.0f;
    #pragma unroll 8
    for (int o = 0; o < HIDD; ++o)
        s += W_edge[h * (16 * HIDD) + d * HIDD + o] * att[h * (3 * HIDD) + 2 * HIDD + o];
    g_w3[t] = s;
}

// ---------------- GEMM1: xw = x @ Wcat, FFMA2 inner loop ---------------------
// 128x128 tile, BK=16, 256 threads, 8x8 reg tile packed as 8x4 u64
__global__ __launch_bounds__(256) void k_gemm_xw(const float* __restrict__ X,
                                                 const float* __restrict__ W) {
    __shared__ float As[16][128];
    __shared__ float Bs[16][128];
    const int bm = blockIdx.x * 128;
    const int bn = blockIdx.y * 128;
    const int tid = threadIdx.x;
    const int tr = tid >> 4, tc = tid & 15;

    u64 acc2[8][4];
    #pragma unroll
    for (int i = 0; i < 8; ++i)
        #pragma unroll
        for (int j = 0; j < 4; ++j) acc2[i][j] = pack2(0.f, 0.f);

    for (int k0 = 0; k0 < CDIM; k0 += 16) {
        #pragma unroll
        for (int it = 0; it < 2; ++it) {
            int f4  = tid + it * 256;
            int row = f4 >> 2;
            int col = (f4 & 3) << 2;
            int gr  = bm + row;
            float4 v = make_float4(0.f, 0.f, 0.f, 0.f);
            if (gr < N_NODES)
                v = *reinterpret_cast<const float4*>(X + (size_t)gr * CDIM + k0 + col);
            As[col + 0][row] = v.x; As[col + 1][row] = v.y;
            As[col + 2][row] = v.z; As[col + 3][row] = v.w;
        }
        #pragma unroll
        for (int it = 0; it < 2; ++it) {
            int f4   = tid + it * 256;
            int krow = f4 >> 5;
            int col  = (f4 & 31) << 2;
            int c    = bn + col;
            int k    = k0 + krow;
            float4 v = *reinterpret_cast<const float4*>(
                W + (size_t)(c >> 6) * (CDIM * HIDD) + (size_t)k * HIDD + (c & 63));
            *reinterpret_cast<float4*>(&Bs[krow][col]) = v;
        }
        __syncthreads();
        #pragma unroll
        for (int k = 0; k < 16; ++k) {
            float4 a0 = *reinterpret_cast<const float4*>(&As[k][tr * 8]);
            float4 a1 = *reinterpret_cast<const float4*>(&As[k][tr * 8 + 4]);
            float4 b0 = *reinterpret_cast<const float4*>(&Bs[k][tc * 8]);
            float4 b1 = *reinterpret_cast<const float4*>(&Bs[k][tc * 8 + 4]);
            float a[8] = {a0.x, a0.y, a0.z, a0.w, a1.x, a1.y, a1.z, a1.w};
            u64 bb0 = pack2(b0.x, b0.y), bb1 = pack2(b0.z, b0.w);
            u64 bb2 = pack2(b1.x, b1.y), bb3 = pack2(b1.z, b1.w);
            #pragma unroll
            for (int i = 0; i < 8; ++i) {
                u64 aa = pack2(a[i], a[i]);
                ffma2(acc2[i][0], aa, bb0);
                ffma2(acc2[i][1], aa, bb1);
                ffma2(acc2[i][2], aa, bb2);
                ffma2(acc2[i][3], aa, bb3);
            }
        }
        __syncthreads();
    }
    #pragma unroll
    for (int i = 0; i < 8; ++i) {
        int gr = bm + tr * 8 + i;
        if (gr >= N_NODES) continue;
        float r0, r1, r2, r3, r4, r5, r6, r7;
        unpack2(acc2[i][0], r0, r1); unpack2(acc2[i][1], r2, r3);
        unpack2(acc2[i][2], r4, r5); unpack2(acc2[i][3], r6, r7);
        *reinterpret_cast<float4*>(g_xw + (size_t)gr * CDIM + bn + tc * 8)
            = make_float4(r0, r1, r2, r3);
        *reinterpret_cast<float4*>(g_xw + (size_t)gr * CDIM + bn + tc * 8 + 4)
            = make_float4(r4, r5, r6, r7);
    }
}

// ---------------- s1/s2: per-node dot of xw with a1/a2 (warp per node) -----
__global__ __launch_bounds__(256) void k_s12(const float* __restrict__ att) {
    __shared__ float a1s[CDIM];
    __shared__ float a2s[CDIM];
    int tid = threadIdx.x;
    {
        int h = tid >> 6, o = tid & 63;
        a1s[tid] = att[h * (3 * HIDD) + o];
        a2s[tid] = att[h * (3 * HIDD) + HIDD + o];
    }
    __syncthreads();
    int warp = tid >> 5, lane = tid & 31;
    long long n = (long long)blockIdx.x * 8 + warp;
    if (n >= N_NODES) return;
    const float4* xp = reinterpret_cast<const float4*>(g_xw + n * CDIM + lane * 8);
    float4 v0 = xp[0], v1 = xp[1];
    int base = lane * 8;
    float p1 = v0.x * a1s[base]     + v0.y * a1s[base + 1] + v0.z * a1s[base + 2] + v0.w * a1s[base + 3]
             + v1.x * a1s[base + 4] + v1.y * a1s[base + 5] + v1.z * a1s[base + 6] + v1.w * a1s[base + 7];
    float p2 = v0.x * a2s[base]     + v0.y * a2s[base + 1] + v0.z * a2s[base + 2] + v0.w * a2s[base + 3]
             + v1.x * a2s[base + 4] + v1.y * a2s[base + 5] + v1.z * a2s[base + 6] + v1.w * a2s[base + 7];
    #pragma unroll
    for (int off = 4; off; off >>= 1) {
        p1 += __shfl_down_sync(0xffffffffu, p1, off, 8);
        p2 += __shfl_down_sync(0xffffffffu, p2, off, 8);
    }
    if ((lane & 7) == 0) {
        int h = lane >> 3;
        g_s1[n * NHEAD + h] = p1;
        g_s2[n * NHEAD + h] = p2;
    }
}

// ---------------- degree histogram -------------------------------------------
__global__ __launch_bounds__(256) void k_deg(const int* __restrict__ ei) {
    long long id = (long long)blockIdx.x * 256 + threadIdx.x;
    if (id >= N_EDGES) return;
    atomicAdd(&g_deg[ei[(long long)N_EDGES + id]], 1);
}

// ---------------- single-block exclusive scan of degrees ---------------------
__global__ __launch_bounds__(SCAN_T) void k_scan() {
    __shared__ int s[SCAN_T];
    int t = threadIdx.x;
    int start = t * SCAN_CHUNK;
    int end = min(start + SCAN_CHUNK, N_NODES);
    int local = 0;
    for (int i = start; i < end; ++i) local += g_deg[i];
    s[t] = local;
    __syncthreads();
    for (int off = 1; off < SCAN_T; off <<= 1) {
        int v = (t >= off) ? s[t - off] : 0;
        __syncthreads();
        s[t] += v;
        __syncthreads();
    }
    int run = s[t] - local;
    for (int i = start; i < end; ++i) {
        g_off[i] = run;
        g_cur[i] = run;
        run += g_deg[i];
    }
}

// ---------------- edge scatter: compute logits, write dst-sorted -------------
__global__ __launch_bounds__(256) void k_scatter(const int* __restrict__ ei,
                                                 const float* __restrict__ eattr) {
    __shared__ float w3s[NHEAD * 16];
    if (threadIdx.x < NHEAD * 16) w3s[threadIdx.x] = g_w3[threadIdx.x];
    __syncthreads();
    long long id = (long long)blockIdx.x * 256 + threadIdx.x;
    if (id >= N_EDGES) return;
    int src = ei[id];
    int dst = ei[(long long)N_EDGES + id];
    const float4* ap = reinterpret_cast<const float4*>(eattr + id * 16);
    float4 e0 = ap[0], e1 = ap[1], e2 = ap[2], e3 = ap[3];
    float attr[16] = {e0.x, e0.y, e0.z, e0.w, e1.x, e1.y, e1.z, e1.w,
                      e2.x, e2.y, e2.z, e2.w, e3.x, e3.y, e3.z, e3.w};
    float4 s1v = *reinterpret_cast<const float4*>(g_s1 + (size_t)dst * NHEAD);
    float4 s2v = *reinterpret_cast<const float4*>(g_s2 + (size_t)src * NHEAD);
    float eh[NHEAD];
    #pragma unroll
    for (int h = 0; h < NHEAD; ++h) {
        float d = 0.0f;
        #pragma unroll
        for (int q = 0; q < 16; ++q) d += attr[q] * w3s[h * 16 + q];
        eh[h] = d;
    }
    eh[0] += s1v.x + s2v.x; eh[1] += s1v.y + s2v.y;
    eh[2] += s1v.z + s2v.z; eh[3] += s1v.w + s2v.w;
    #pragma unroll
    for (int h = 0; h < NHEAD; ++h)
        eh[h] = (eh[h] >= 0.0f) ? eh[h] : NEG_SLOPE * eh[h];
    int pos = atomicAdd(&g_cur[dst], 1);
    g_se[pos] = make_float4(eh[0], eh[1], eh[2], eh[3]);
    g_ss[pos] = src;
}

// ---------------- aggregation: warp per node, no atomics, unroll x2 ----------
__global__ __launch_bounds__(256) void k_agg() {
    int warp = threadIdx.x >> 5, lane = threadIdx.x & 31;
    int n = blockIdx.x * 8 + warp;
    if (n >= N_NODES) return;
    int base = g_off[n];
    int deg  = g_deg[n];
    int h    = lane >> 3;
    int col  = lane * 8;

    float4 mx = make_float4(-3.0e38f, -3.0e38f, -3.0e38f, -3.0e38f);
    for (int i = lane; i < deg; i += 32) {
        float4 ev = g_se[base + i];
        mx.x = fmaxf(mx.x, ev.x); mx.y = fmaxf(mx.y, ev.y);
        mx.z = fmaxf(mx.z, ev.z); mx.w = fmaxf(mx.w, ev.w);
    }
    #pragma unroll
    for (int off = 16; off; off >>= 1) {
        mx.x = fmaxf(mx.x, __shfl_xor_sync(0xffffffffu, mx.x, off));
        mx.y = fmaxf(mx.y, __shfl_xor_sync(0xffffffffu, mx.y, off));
        mx.z = fmaxf(mx.z, __shfl_xor_sync(0xffffffffu, mx.z, off));
        mx.w = fmaxf(mx.w, __shfl_xor_sync(0xffffffffu, mx.w, off));
    }
    float m_h = (h == 0) ? mx.x : (h == 1) ? mx.y : (h == 2) ? mx.z : mx.w;

    float a0x = 0.f, a0y = 0.f, a0z = 0.f, a0w = 0.f;
    float a1x = 0.f, a1y = 0.f, a1z = 0.f, a1w = 0.f;
    float sum = 0.f;

    int i = 0;
    for (; i + 2 <= deg; i += 2) {
        float4 evA = __ldg(&g_se[base + i]);
        float4 evB = __ldg(&g_se[base + i + 1]);
        int srcA = __ldg(&g_ss[base + i]);
        int srcB = __ldg(&g_ss[base + i + 1]);
        float eA = (h == 0) ? evA.x : (h == 1) ? evA.y : (h == 2) ? evA.z : evA.w;
        float eB = (h == 0) ? evB.x : (h == 1) ? evB.y : (h == 2) ? evB.z : evB.w;
        float exA = __expf(eA - m_h);
        float exB = __expf(eB - m_h);
        sum += exA + exB;
        const float4* xpA = reinterpret_cast<const float4*>(g_xw + (size_t)srcA * CDIM + col);
        const float4* xpB = reinterpret_cast<const float4*>(g_xw + (size_t)srcB * CDIM + col);
        float4 vA0 = __ldg(xpA), vA1 = __ldg(xpA + 1);
        float4 vB0 = __ldg(xpB), vB1 = __ldg(xpB + 1);
        a0x += vA0.x * exA; a0y += vA0.y * exA; a0z += vA0.z * exA; a0w += vA0.w * exA;
        a1x += vA1.x * exA; a1y += vA1.y * exA; a1z += vA1.z * exA; a1w += vA1.w * exA;
        a0x += vB0.x * exB; a0y += vB0.y * exB; a0z += vB0.z * exB; a0w += vB0.w * exB;
        a1x += vB1.x * exB; a1y += vB1.y * exB; a1z += vB1.z * exB; a1w += vB1.w * exB;
    }
    if (i < deg) {
        float4 ev = __ldg(&g_se[base + i]);
        int src = __ldg(&g_ss[base + i]);
        float e_h = (h == 0) ? ev.x : (h == 1) ? ev.y : (h == 2) ? ev.z : ev.w;
        float ex = __expf(e_h - m_h);
        sum += ex;
        const float4* xp = reinterpret_cast<const float4*>(g_xw + (size_t)src * CDIM + col);
        float4 v0 = __ldg(xp), v1 = __ldg(xp + 1);
        a0x += v0.x * ex; a0y += v0.y * ex; a0z += v0.z * ex; a0w += v0.w * ex;
        a1x += v1.x * ex; a1y += v1.y * ex; a1z += v1.z * ex; a1w += v1.w * ex;
    }
    float inv = 1.0f / (sum + 1e-16f);
    float* dp = g_acc + (size_t)n * CDIM + col;
    *reinterpret_cast<float4*>(dp)     = make_float4(a0x * inv, a0y * inv, a0z * inv, a0w * inv);
    *reinterpret_cast<float4*>(dp + 4) = make_float4(a1x * inv, a1y * inv, a1z * inv, a1w * inv);
}

// ---------------- GEMM2: out = elu(acc @ proj_w + b), FFMA2 inner loop -------
__global__ __launch_bounds__(256) void k_gemm_out(const float* __restrict__ PW,
                                                  const float* __restrict__ PB,
                                                  float* __restrict__ out) {
    __shared__ float As[16][128];
    __shared__ float Bs[16][128];
    const int bm = blockIdx.x * 128;
    const int bn = blockIdx.y * 128;
    const int tid = threadIdx.x;
    const int tr = tid >> 4, tc = tid & 15;

    u64 acc2[8][4];
    #pragma unroll
    for (int i = 0; i < 8; ++i)
        #pragma unroll
        for (int j = 0; j < 4; ++j) acc2[i][j] = pack2(0.f, 0.f);

    for (int k0 = 0; k0 < CDIM; k0 += 16) {
        #pragma unroll
        for (int it = 0; it < 2; ++it) {
            int f4  = tid + it * 256;
            int row = f4 >> 2;
            int col = (f4 & 3) << 2;
            int gr  = bm + row;
            float4 v = make_float4(0.f, 0.f, 0.f, 0.f);
            if (gr < N_NODES)
                v = *reinterpret_cast<const float4*>(g_acc + (size_t)gr * CDIM + k0 + col);
            As[col + 0][row] = v.x; As[col + 1][row] = v.y;
            As[col + 2][row] = v.z; As[col + 3][row] = v.w;
        }
        #pragma unroll
        for (int it = 0; it < 2; ++it) {
            int f4   = tid + it * 256;
            int krow = f4 >> 5;
            int col  = (f4 & 31) << 2;
            int c    = bn + col;
            int k    = k0 + krow;
            float4 v = *reinterpret_cast<const float4*>(PW + (size_t)k * CDIM + c);
            *reinterpret_cast<float4*>(&Bs[krow][col]) = v;
        }
        __syncthreads();
        #pragma unroll
        for (int k = 0; k < 16; ++k) {
            float4 a0 = *reinterpret_cast<const float4*>(&As[k][tr * 8]);
            float4 a1 = *reinterpret_cast<const float4*>(&As[k][tr * 8 + 4]);
            float4 b0 = *reinterpret_cast<const float4*>(&Bs[k][tc * 8]);
            float4 b1 = *reinterpret_cast<const float4*>(&Bs[k][tc * 8 + 4]);
            float a[8] = {a0.x, a0.y, a0.z, a0.w, a1.x, a1.y, a1.z, a1.w};
            u64 bb0 = pack2(b0.x, b0.y), bb1 = pack2(b0.z, b0.w);
            u64 bb2 = pack2(b1.x, b1.y), bb3 = pack2(b1.z, b1.w);
            #pragma unroll
            for (int i = 0; i < 8; ++i) {
                u64 aa = pack2(a[i], a[i]);
                ffma2(acc2[i][0], aa, bb0);
                ffma2(acc2[i][1], aa, bb1);
                ffma2(acc2[i][2], aa, bb2);
                ffma2(acc2[i][3], aa, bb3);
            }
        }
        __syncthreads();
    }
    float4 bb0 = *reinterpret_cast<const float4*>(PB + bn + tc * 8);
    float4 bb1 = *reinterpret_cast<const float4*>(PB + bn + tc * 8 + 4);
    #pragma unroll
    for (int i = 0; i < 8; ++i) {
        int gr = bm + tr * 8 + i;
        if (gr >= N_NODES) continue;
        float r0, r1, r2, r3, r4, r5, r6, r7;
        unpack2(acc2[i][0], r0, r1); unpack2(acc2[i][1], r2, r3);
        unpack2(acc2[i][2], r4, r5); unpack2(acc2[i][3], r6, r7);
        r0 += bb0.x; r1 += bb0.y; r2 += bb0.z; r3 += bb0.w;
        r4 += bb1.x; r5 += bb1.y; r6 += bb1.z; r7 += bb1.w;
        r0 = (r0 > 0.f) ? r0 : expm1f(r0);
        r1 = (r1 > 0.f) ? r1 : expm1f(r1);
        r2 = (r2 > 0.f) ? r2 : expm1f(r2);
        r3 = (r3 > 0.f) ? r3 : expm1f(r3);
        r4 = (r4 > 0.f) ? r4 : expm1f(r4);
        r5 = (r5 > 0.f) ? r5 : expm1f(r5);
        r6 = (r6 > 0.f) ? r6 : expm1f(r6);
        r7 = (r7 > 0.f) ? r7 : expm1f(r7);
        *reinterpret_cast<float4*>(out + (size_t)gr * CDIM + bn + tc * 8)
            = make_float4(r0, r1, r2, r3);
        *reinterpret_cast<float4*>(out + (size_t)gr * CDIM + bn + tc * 8 + 4)
            = make_float4(r4, r5, r6, r7);
    }
}

// ---------------- launch ------------------------------------------------------
extern "C" void kernel_launch(void* const* d_in, const int* in_sizes, int n_in,
                              void* d_out, int out_size) {
    const float* x      = (const float*)d_in[0];
    const int*   ei     = (const int*)d_in[1];
    const float* eattr  = (const float*)d_in[2];
    const float* W      = (const float*)d_in[3];
    const float* W_edge = (const float*)d_in[4];
    const float* att    = (const float*)d_in[5];
    const float* proj_w = (const float*)d_in[6];
    const float* proj_b = (const float*)d_in[7];
    float*       out    = (float*)d_out;

    k_zero_deg<<<(N_NODES + 255) / 256, 256>>>();
    k_w3<<<1, 64>>>(W_edge, att);

    dim3 g1((N_NODES + 127) / 128, CDIM / 128);
    k_gemm_xw<<<g1, 256>>>(x, W);

    k_s12<<<(N_NODES + 7) / 8, 256>>>(att);

    k_deg<<<(N_EDGES + 255) / 256, 256>>>(ei);
    k_scan<<<1, SCAN_T>>>();
    k_scatter<<<(N_EDGES + 255) / 256, 256>>>(ei, eattr);

    k_agg<<<(N_NODES + 7) / 8, 256>>>();

    k_gemm_out<<<g1, 256>>>(proj_w, proj_b, out);
}

// round 13
// speedup vs baseline: 2.8889x; 1.0200x over previous
#include <cuda_runtime.h>
#include <cuda_fp16.h>

#define N_NODES 100000
#define N_EDGES 1600000
#define NHEAD 4
#define HIDD 64
#define CDIM 256   // H*HID = IN_DIM = OUT_DIM
#define KHALF 128  // CDIM/2 half2 words per row
#define NEG_SLOPE 0.2f
#define SCAN_T 1024
#define SCAN_CHUNK ((N_NODES + SCAN_T - 1) / SCAN_T)   // 98

typedef unsigned long long u64;
typedef unsigned int u32;

// ---------------- scratch (static device globals; no runtime allocation) ----
__device__ float  g_xw [ (size_t)N_NODES * CDIM ];   // fp32 xw (for s12)
__device__ u32    g_xwh[ (size_t)N_NODES * KHALF ];  // half2 mirror of xw (for agg gather)
__device__ float  g_acc[ (size_t)N_NODES * CDIM ];
__device__ float  g_s1 [ (size_t)N_NODES * NHEAD ];
__device__ float  g_s2 [ (size_t)N_NODES * NHEAD ];
__device__ float  g_w3 [ NHEAD * 16 ];
__device__ int    g_deg[ N_NODES ];
__device__ int    g_off[ N_NODES ];
__device__ int    g_cur[ N_NODES ];
__device__ float4 g_se [ N_EDGES ];
__device__ int    g_ss [ N_EDGES ];

// ---------------- packed f32x2 helpers (sm_100+) -----------------------------
__device__ __forceinline__ void ffma2(u64& d, u64 a, u64 b) {
    asm("fma.rn.f32x2 %0, %1, %2, %0;" : "+l"(d) : "l"(a), "l"(b));
}
__device__ __forceinline__ u64 pack2(float lo, float hi) {
    u64 r; asm("mov.b64 %0, {%1, %2};" : "=l"(r) : "f"(lo), "f"(hi)); return r;
}
__device__ __forceinline__ void unpack2(u64 v, float& lo, float& hi) {
    asm("mov.b64 {%0, %1}, %2;" : "=f"(lo), "=f"(hi) : "l"(v));
}
__device__ __forceinline__ u32 f2h2(float a, float b) {
    __half2 v = __floats2half2_rn(a, b);
    return *reinterpret_cast<u32*>(&v);
}
__device__ __forceinline__ float2 h22f2(u32 h) {
    __half2 v = *reinterpret_cast<__half2*>(&h);
    return __half22float2(v);
}

// ---------------- zero degree counters --------------------------------------
__global__ void k_zero_deg() {
    int i = blockIdx.x * blockDim.x + threadIdx.x;
    if (i < N_NODES) g_deg[i] = 0;
}

// ---------------- w3[h][d] = sum_o W_edge[h][d][o] * a3[h][o] ---------------
__global__ void k_w3(const float* __restrict__ W_edge, const float* __restrict__ att) {
    int t = threadIdx.x;
    if (t >= NHEAD * 16) return;
    int h = t >> 4, d = t & 15;
    float s = 0.0f;
    #pragma unroll 8
    for (int o = 0; o < HIDD; ++o)
        s += W_edge[h * (16 * HIDD) + d * HIDD + o] * att[h * (3 * HIDD) + 2 * HIDD + o];
    g_w3[t] = s;
}

// ---------------- GEMM1: xw = x @ Wcat, FFMA2, BK=32 -------------------------
// 128x128 tile, 256 threads, 8x8 reg tile packed as 8x4 u64
__global__ __launch_bounds__(256) void k_gemm_xw(const float* __restrict__ X,
                                                 const float* __restrict__ W) {
    __shared__ float As[32][128];
    __shared__ float Bs[32][128];
    const int bm = blockIdx.x * 128;
    const int bn = blockIdx.y * 128;
    const int tid = threadIdx.x;
    const int tr = tid >> 4, tc = tid & 15;

    u64 acc2[8][4];
    #pragma unroll
    for (int i = 0; i < 8; ++i)
        #pragma unroll
        for (int j = 0; j < 4; ++j) acc2[i][j] = pack2(0.f, 0.f);

    for (int k0 = 0; k0 < CDIM; k0 += 32) {
        #pragma unroll
        for (int it = 0; it < 4; ++it) {
            int f4  = tid + it * 256;      // 0..1023
            int row = f4 >> 3;             // 0..127
            int col = (f4 & 7) << 2;       // 0..28
            int gr  = bm + row;
            float4 v = make_float4(0.f, 0.f, 0.f, 0.f);
            if (gr < N_NODES)
                v = *reinterpret_cast<const float4*>(X + (size_t)gr * CDIM + k0 + col);
            As[col + 0][row] = v.x; As[col + 1][row] = v.y;
            As[col + 2][row] = v.z; As[col + 3][row] = v.w;
        }
        #pragma unroll
        for (int it = 0; it < 4; ++it) {
            int f4   = tid + it * 256;
            int krow = f4 >> 5;            // 0..31
            int col  = (f4 & 31) << 2;     // 0..124
            int c    = bn + col;
            int k    = k0 + krow;
            float4 v = *reinterpret_cast<const float4*>(
                W + (size_t)(c >> 6) * (CDIM * HIDD) + (size_t)k * HIDD + (c & 63));
            *reinterpret_cast<float4*>(&Bs[krow][col]) = v;
        }
        __syncthreads();
        #pragma unroll
        for (int k = 0; k < 32; ++k) {
            float4 a0 = *reinterpret_cast<const float4*>(&As[k][tr * 8]);
            float4 a1 = *reinterpret_cast<const float4*>(&As[k][tr * 8 + 4]);
            float4 b0 = *reinterpret_cast<const float4*>(&Bs[k][tc * 8]);
            float4 b1 = *reinterpret_cast<const float4*>(&Bs[k][tc * 8 + 4]);
            float a[8] = {a0.x, a0.y, a0.z, a0.w, a1.x, a1.y, a1.z, a1.w};
            u64 bb0 = pack2(b0.x, b0.y), bb1 = pack2(b0.z, b0.w);
            u64 bb2 = pack2(b1.x, b1.y), bb3 = pack2(b1.z, b1.w);
            #pragma unroll
            for (int i = 0; i < 8; ++i) {
                u64 aa = pack2(a[i], a[i]);
                ffma2(acc2[i][0], aa, bb0);
                ffma2(acc2[i][1], aa, bb1);
                ffma2(acc2[i][2], aa, bb2);
                ffma2(acc2[i][3], aa, bb3);
            }
        }
        __syncthreads();
    }
    #pragma unroll
    for (int i = 0; i < 8; ++i) {
        int gr = bm + tr * 8 + i;
        if (gr >= N_NODES) continue;
        float r0, r1, r2, r3, r4, r5, r6, r7;
        unpack2(acc2[i][0], r0, r1); unpack2(acc2[i][1], r2, r3);
        unpack2(acc2[i][2], r4, r5); unpack2(acc2[i][3], r6, r7);
        *reinterpret_cast<float4*>(g_xw + (size_t)gr * CDIM + bn + tc * 8)
            = make_float4(r0, r1, r2, r3);
        *reinterpret_cast<float4*>(g_xw + (size_t)gr * CDIM + bn + tc * 8 + 4)
            = make_float4(r4, r5, r6, r7);
        // half2 mirror for the aggregation gather
        *reinterpret_cast<uint4*>(g_xwh + (size_t)gr * KHALF + (bn + tc * 8) / 2)
            = make_uint4(f2h2(r0, r1), f2h2(r2, r3), f2h2(r4, r5), f2h2(r6, r7));
    }
}

// ---------------- s1/s2: per-node dot of xw with a1/a2 (warp per node) -----
__global__ __launch_bounds__(256) void k_s12(const float* __restrict__ att) {
    __shared__ float a1s[CDIM];
    __shared__ float a2s[CDIM];
    int tid = threadIdx.x;
    {
        int h = tid >> 6, o = tid & 63;
        a1s[tid] = att[h * (3 * HIDD) + o];
        a2s[tid] = att[h * (3 * HIDD) + HIDD + o];
    }
    __syncthreads();
    int warp = tid >> 5, lane = tid & 31;
    long long n = (long long)blockIdx.x * 8 + warp;
    if (n >= N_NODES) return;
    const float4* xp = reinterpret_cast<const float4*>(g_xw + n * CDIM + lane * 8);
    float4 v0 = xp[0], v1 = xp[1];
    int base = lane * 8;
    float p1 = v0.x * a1s[base]     + v0.y * a1s[base + 1] + v0.z * a1s[base + 2] + v0.w * a1s[base + 3]
             + v1.x * a1s[base + 4] + v1.y * a1s[base + 5] + v1.z * a1s[base + 6] + v1.w * a1s[base + 7];
    float p2 = v0.x * a2s[base]     + v0.y * a2s[base + 1] + v0.z * a2s[base + 2] + v0.w * a2s[base + 3]
             + v1.x * a2s[base + 4] + v1.y * a2s[base + 5] + v1.z * a2s[base + 6] + v1.w * a2s[base + 7];
    #pragma unroll
    for (int off = 4; off; off >>= 1) {
        p1 += __shfl_down_sync(0xffffffffu, p1, off, 8);
        p2 += __shfl_down_sync(0xffffffffu, p2, off, 8);
    }
    if ((lane & 7) == 0) {
        int h = lane >> 3;
        g_s1[n * NHEAD + h] = p1;
        g_s2[n * NHEAD + h] = p2;
    }
}

// ---------------- degree histogram -------------------------------------------
__global__ __launch_bounds__(256) void k_deg(const int* __restrict__ ei) {
    long long id = (long long)blockIdx.x * 256 + threadIdx.x;
    if (id >= N_EDGES) return;
    atomicAdd(&g_deg[ei[(long long)N_EDGES + id]], 1);
}

// ---------------- single-block exclusive scan of degrees ---------------------
__global__ __launch_bounds__(SCAN_T) void k_scan() {
    __shared__ int s[SCAN_T];
    int t = threadIdx.x;
    int start = t * SCAN_CHUNK;
    int end = min(start + SCAN_CHUNK, N_NODES);
    int local = 0;
    for (int i = start; i < end; ++i) local += g_deg[i];
    s[t] = local;
    __syncthreads();
    for (int off = 1; off < SCAN_T; off <<= 1) {
        int v = (t >= off) ? s[t - off] : 0;
        __syncthreads();
        s[t] += v;
        __syncthreads();
    }
    int run = s[t] - local;
    for (int i = start; i < end; ++i) {
        g_off[i] = run;
        g_cur[i] = run;
        run += g_deg[i];
    }
}

// ---------------- edge scatter: compute logits, write dst-sorted -------------
__global__ __launch_bounds__(256) void k_scatter(const int* __restrict__ ei,
                                                 const float* __restrict__ eattr) {
    __shared__ float w3s[NHEAD * 16];
    if (threadIdx.x < NHEAD * 16) w3s[threadIdx.x] = g_w3[threadIdx.x];
    __syncthreads();
    long long id = (long long)blockIdx.x * 256 + threadIdx.x;
    if (id >= N_EDGES) return;
    int src = ei[id];
    int dst = ei[(long long)N_EDGES + id];
    const float4* ap = reinterpret_cast<const float4*>(eattr + id * 16);
    float4 e0 = ap[0], e1 = ap[1], e2 = ap[2], e3 = ap[3];
    float attr[16] = {e0.x, e0.y, e0.z, e0.w, e1.x, e1.y, e1.z, e1.w,
                      e2.x, e2.y, e2.z, e2.w, e3.x, e3.y, e3.z, e3.w};
    float4 s1v = *reinterpret_cast<const float4*>(g_s1 + (size_t)dst * NHEAD);
    float4 s2v = *reinterpret_cast<const float4*>(g_s2 + (size_t)src * NHEAD);
    float eh[NHEAD];
    #pragma unroll
    for (int h = 0; h < NHEAD; ++h) {
        float d = 0.0f;
        #pragma unroll
        for (int q = 0; q < 16; ++q) d += attr[q] * w3s[h * 16 + q];
        eh[h] = d;
    }
    eh[0] += s1v.x + s2v.x; eh[1] += s1v.y + s2v.y;
    eh[2] += s1v.z + s2v.z; eh[3] += s1v.w + s2v.w;
    #pragma unroll
    for (int h = 0; h < NHEAD; ++h)
        eh[h] = (eh[h] >= 0.0f) ? eh[h] : NEG_SLOPE * eh[h];
    int pos = atomicAdd(&g_cur[dst], 1);
    g_se[pos] = make_float4(eh[0], eh[1], eh[2], eh[3]);
    g_ss[pos] = src;
}

// ---------------- aggregation: warp per node, fp16 gather, unroll x2 ---------
// lane l handles cols [l*8, l*8+8); head = l>>3
__global__ __launch_bounds__(256) void k_agg() {
    int warp = threadIdx.x >> 5, lane = threadIdx.x & 31;
    int n = blockIdx.x * 8 + warp;
    if (n >= N_NODES) return;
    int base = g_off[n];
    int deg  = g_deg[n];
    int h    = lane >> 3;
    int colh = lane * 4;   // u32 (half2) index of this lane's 8 columns

    // pass 1: per-head max
    float4 mx = make_float4(-3.0e38f, -3.0e38f, -3.0e38f, -3.0e38f);
    for (int i = lane; i < deg; i += 32) {
        float4 ev = g_se[base + i];
        mx.x = fmaxf(mx.x, ev.x); mx.y = fmaxf(mx.y, ev.y);
        mx.z = fmaxf(mx.z, ev.z); mx.w = fmaxf(mx.w, ev.w);
    }
    #pragma unroll
    for (int off = 16; off; off >>= 1) {
        mx.x = fmaxf(mx.x, __shfl_xor_sync(0xffffffffu, mx.x, off));
        mx.y = fmaxf(mx.y, __shfl_xor_sync(0xffffffffu, mx.y, off));
        mx.z = fmaxf(mx.z, __shfl_xor_sync(0xffffffffu, mx.z, off));
        mx.w = fmaxf(mx.w, __shfl_xor_sync(0xffffffffu, mx.w, off));
    }
    float m_h = (h == 0) ? mx.x : (h == 1) ? mx.y : (h == 2) ? mx.z : mx.w;

    // pass 2: exp + sum + weighted accumulate from fp16 mirror
    float a0x = 0.f, a0y = 0.f, a0z = 0.f, a0w = 0.f;
    float a1x = 0.f, a1y = 0.f, a1z = 0.f, a1w = 0.f;
    float sum = 0.f;

    int i = 0;
    for (; i + 2 <= deg; i += 2) {
        float4 evA = __ldg(&g_se[base + i]);
        float4 evB = __ldg(&g_se[base + i + 1]);
        int srcA = __ldg(&g_ss[base + i]);
        int srcB = __ldg(&g_ss[base + i + 1]);
        float eA = (h == 0) ? evA.x : (h == 1) ? evA.y : (h == 2) ? evA.z : evA.w;
        float eB = (h == 0) ? evB.x : (h == 1) ? evB.y : (h == 2) ? evB.z : evB.w;
        float exA = __expf(eA - m_h);
        float exB = __expf(eB - m_h);
        sum += exA + exB;
        uint4 hA = __ldg(reinterpret_cast<const uint4*>(g_xwh + (size_t)srcA * KHALF + colh));
        uint4 hB = __ldg(reinterpret_cast<const uint4*>(g_xwh + (size_t)srcB * KHALF + colh));
        float2 fA0 = h22f2(hA.x), fA1 = h22f2(hA.y), fA2 = h22f2(hA.z), fA3 = h22f2(hA.w);
        float2 fB0 = h22f2(hB.x), fB1 = h22f2(hB.y), fB2 = h22f2(hB.z), fB3 = h22f2(hB.w);
        a0x += fA0.x * exA; a0y += fA0.y * exA; a0z += fA1.x * exA; a0w += fA1.y * exA;
        a1x += fA2.x * exA; a1y += fA2.y * exA; a1z += fA3.x * exA; a1w += fA3.y * exA;
        a0x += fB0.x * exB; a0y += fB0.y * exB; a0z += fB1.x * exB; a0w += fB1.y * exB;
        a1x += fB2.x * exB; a1y += fB2.y * exB; a1z += fB3.x * exB; a1w += fB3.y * exB;
    }
    if (i < deg) {
        float4 ev = __ldg(&g_se[base + i]);
        int src = __ldg(&g_ss[base + i]);
        float e_h = (h == 0) ? ev.x : (h == 1) ? ev.y : (h == 2) ? ev.z : ev.w;
        float ex = __expf(e_h - m_h);
        sum += ex;
        uint4 hv = __ldg(reinterpret_cast<const uint4*>(g_xwh + (size_t)src * KHALF + colh));
        float2 f0 = h22f2(hv.x), f1 = h22f2(hv.y), f2 = h22f2(hv.z), f3 = h22f2(hv.w);
        a0x += f0.x * ex; a0y += f0.y * ex; a0z += f1.x * ex; a0w += f1.y * ex;
        a1x += f2.x * ex; a1y += f2.y * ex; a1z += f3.x * ex; a1w += f3.y * ex;
    }
    float inv = 1.0f / (sum + 1e-16f);
    float* dp = g_acc + (size_t)n * CDIM + lane * 8;
    *reinterpret_cast<float4*>(dp)     = make_float4(a0x * inv, a0y * inv, a0z * inv, a0w * inv);
    *reinterpret_cast<float4*>(dp + 4) = make_float4(a1x * inv, a1y * inv, a1z * inv, a1w * inv);
}

// ---------------- GEMM2: out = elu(acc @ proj_w + b), FFMA2, BK=32 -----------
__global__ __launch_bounds__(256) void k_gemm_out(const float* __restrict__ PW,
                                                  const float* __restrict__ PB,
                                                  float* __restrict__ out) {
    __shared__ float As[32][128];
    __shared__ float Bs[32][128];
    const int bm = blockIdx.x * 128;
    const int bn = blockIdx.y * 128;
    const int tid = threadIdx.x;
    const int tr = tid >> 4, tc = tid & 15;

    u64 acc2[8][4];
    #pragma unroll
    for (int i = 0; i < 8; ++i)
        #pragma unroll
        for (int j = 0; j < 4; ++j) acc2[i][j] = pack2(0.f, 0.f);

    for (int k0 = 0; k0 < CDIM; k0 += 32) {
        #pragma unroll
        for (int it = 0; it < 4; ++it) {
            int f4  = tid + it * 256;
            int row = f4 >> 3;
            int col = (f4 & 7) << 2;
            int gr  = bm + row;
            float4 v = make_float4(0.f, 0.f, 0.f, 0.f);
            if (gr < N_NODES)
                v = *reinterpret_cast<const float4*>(g_acc + (size_t)gr * CDIM + k0 + col);
            As[col + 0][row] = v.x; As[col + 1][row] = v.y;
            As[col + 2][row] = v.z; As[col + 3][row] = v.w;
        }
        #pragma unroll
        for (int it = 0; it < 4; ++it) {
            int f4   = tid + it * 256;
            int krow = f4 >> 5;
            int col  = (f4 & 31) << 2;
            int c    = bn + col;
            int k    = k0 + krow;
            float4 v = *reinterpret_cast<const float4*>(PW + (size_t)k * CDIM + c);
            *reinterpret_cast<float4*>(&Bs[krow][col]) = v;
        }
        __syncthreads();
        #pragma unroll
        for (int k = 0; k < 32; ++k) {
            float4 a0 = *reinterpret_cast<const float4*>(&As[k][tr * 8]);
            float4 a1 = *reinterpret_cast<const float4*>(&As[k][tr * 8 + 4]);
            float4 b0 = *reinterpret_cast<const float4*>(&Bs[k][tc * 8]);
            float4 b1 = *reinterpret_cast<const float4*>(&Bs[k][tc * 8 + 4]);
            float a[8] = {a0.x, a0.y, a0.z, a0.w, a1.x, a1.y, a1.z, a1.w};
            u64 bb0 = pack2(b0.x, b0.y), bb1 = pack2(b0.z, b0.w);
            u64 bb2 = pack2(b1.x, b1.y), bb3 = pack2(b1.z, b1.w);
            #pragma unroll
            for (int i = 0; i < 8; ++i) {
                u64 aa = pack2(a[i], a[i]);
                ffma2(acc2[i][0], aa, bb0);
                ffma2(acc2[i][1], aa, bb1);
                ffma2(acc2[i][2], aa, bb2);
                ffma2(acc2[i][3], aa, bb3);
            }
        }
        __syncthreads();
    }
    float4 bb0 = *reinterpret_cast<const float4*>(PB + bn + tc * 8);
    float4 bb1 = *reinterpret_cast<const float4*>(PB + bn + tc * 8 + 4);
    #pragma unroll
    for (int i = 0; i < 8; ++i) {
        int gr = bm + tr * 8 + i;
        if (gr >= N_NODES) continue;
        float r0, r1, r2, r3, r4, r5, r6, r7;
        unpack2(acc2[i][0], r0, r1); unpack2(acc2[i][1], r2, r3);
        unpack2(acc2[i][2], r4, r5); unpack2(acc2[i][3], r6, r7);
        r0 += bb0.x; r1 += bb0.y; r2 += bb0.z; r3 += bb0.w;
        r4 += bb1.x; r5 += bb1.y; r6 += bb1.z; r7 += bb1.w;
        r0 = (r0 > 0.f) ? r0 : expm1f(r0);
        r1 = (r1 > 0.f) ? r1 : expm1f(r1);
        r2 = (r2 > 0.f) ? r2 : expm1f(r2);
        r3 = (r3 > 0.f) ? r3 : expm1f(r3);
        r4 = (r4 > 0.f) ? r4 : expm1f(r4);
        r5 = (r5 > 0.f) ? r5 : expm1f(r5);
        r6 = (r6 > 0.f) ? r6 : expm1f(r6);
        r7 = (r7 > 0.f) ? r7 : expm1f(r7);
        *reinterpret_cast<float4*>(out + (size_t)gr * CDIM + bn + tc * 8)
            = make_float4(r0, r1, r2, r3);
        *reinterpret_cast<float4*>(out + (size_t)gr * CDIM + bn + tc * 8 + 4)
            = make_float4(r4, r5, r6, r7);
    }
}

// ---------------- launch ------------------------------------------------------
extern "C" void kernel_launch(void* const* d_in, const int* in_sizes, int n_in,
                              void* d_out, int out_size) {
    const float* x      = (const float*)d_in[0];
    const int*   ei     = (const int*)d_in[1];
    const float* eattr  = (const float*)d_in[2];
    const float* W      = (const float*)d_in[3];
    const float* W_edge = (const float*)d_in[4];
    const float* att    = (const float*)d_in[5];
    const float* proj_w = (const float*)d_in[6];
    const float* proj_b = (const float*)d_in[7];
    float*       out    = (float*)d_out;

    k_zero_deg<<<(N_NODES + 255) / 256, 256>>>();
    k_w3<<<1, 64>>>(W_edge, att);

    dim3 g1((N_NODES + 127) / 128, CDIM / 128);
    k_gemm_xw<<<g1, 256>>>(x, W);

    k_s12<<<(N_NODES + 7) / 8, 256>>>(att);

    k_deg<<<(N_EDGES + 255) / 256, 256>>>(ei);
    k_scan<<<1, SCAN_T>>>();
    k_scatter<<<(N_EDGES + 255) / 256, 256>>>(ei, eattr);

    k_agg<<<(N_NODES + 7) / 8, 256>>>();

    k_gemm_out<<<g1, 256>>>(proj_w, proj_b, out);
}